// round 4
// baseline (speedup 1.0000x reference)
#include <cuda_runtime.h>

#define NC    32
#define NPAR  4
#define NCH   7
#define NVOX  884736        // 96*96*96
#define NB    2
#define TPB   256
#define VPT   8
#define TILE  (TPB*VPT)     // 2048
#define NBLKX (NVOX/TILE)   // 432 exact
#define NBLK  (NBLKX*NB)    // 864

// global accumulators (zero-init at load; last block resets after use)
// g_f layout: [0..31] denomA, [32..63] inter, [64] ce, [65] vw, [66..69] inter_s, [70..73] tgt_s
__device__ float        g_f[NB][74];
__device__ int          g_sib[NB];
__device__ unsigned     g_hist[NB][NC*NC];
__device__ unsigned int g_count;

__device__ __forceinline__ float wred(float v) {
#pragma unroll
    for (int o = 16; o > 0; o >>= 1) v += __shfl_xor_sync(0xffffffffu, v, o);
    return v;
}

__global__ __launch_bounds__(TPB, 2)
void k_all(const float* __restrict__ img, const int* __restrict__ tgt,
           const int* __restrict__ msk, float* __restrict__ out)
{
    const int b    = blockIdx.y;
    const int tid  = threadIdx.x;
    const int lane = tid & 31;

    __shared__ float sh_dA[NC], sh_in[NC];
    __shared__ float sh_misc[10];      // ce, vw, is[4], ts[4]
    __shared__ int   sh_sib;
    __shared__ unsigned sh_hist[NC*NC];
    __shared__ float sh_mf[NC];
    __shared__ int   sh_last;

    for (int i = tid; i < NC*NC; i += TPB) sh_hist[i] = 0u;
    if (tid < NC) {
        sh_dA[tid] = 0.f; sh_in[tid] = 0.f;
        sh_mf[tid] = (msk[b*NC + tid] != 0) ? 1.f : 0.f;
    }
    if (tid < 10) sh_misc[tid] = 0.f;
    if (tid == 0) { sh_sib = 0; sh_last = 0; }
    __syncthreads();

    const int v0 = blockIdx.x * TILE + tid;
    const float* base = img + (size_t)b * NC * NVOX;

    // grouped channel pointers: anchor channels {2,7,12,17,22,27,30}
    // every logit load is [ptr +/- k*NVOX*4] with |imm| <= 2*NVOX*4 = 7.08MB < 8.38MB
    const float* pg[7];
#pragma unroll
    for (int g = 0; g < 6; g++) pg[g] = base + (size_t)(5*g + 2) * NVOX + v0;
    pg[6] = base + (size_t)30 * NVOX + v0;
    const float* pbase = base + v0;                       // for CE reloads
    const int*   tptr  = tgt + (size_t)b * NVOX + v0;
    float*       pptr  = out + 6 + NB*NC*3 + (size_t)b * NVOX + v0;

    float accA[NC];
#pragma unroll
    for (int c = 0; c < NC; c++) accA[c] = 0.f;
    float a_ce = 0.f, a_vw = 0.f;
    float a_is[4] = {0,0,0,0};
    float a_ts[4] = {0,0,0,0};
    int   a_sib = 0;

    const float L10_LO = -16.11809565f;   // log(1e-7)
    const float L10_HI = -1.0000001e-7f;  // log(1 - 1e-7)

#pragma unroll 1
    for (int it = 0; it < VPT; it++) {
        const int y = *tptr;
        const bool valid = (y != 255);
        const int ys = valid ? y : 0;
        const int ypar = (ys >= NPAR) ? (ys - NPAR) / NCH : -1;

        // load all 32 logits via grouped pointers (compile-time immediates)
        float x[NC];
#pragma unroll
        for (int c = 0; c < NC; c++) {
            const int g   = (c < 30) ? (c / 5) : 6;
            const int anc = (g < 6) ? (5*g + 2) : 30;
            x[c] = pg[g][(ptrdiff_t)(c - anc) * NVOX];
        }

        // argmax over leaves 4..31 on raw logits (first max wins -> strict >)
        int am = NPAR; float bmv = x[NPAR];
#pragma unroll
        for (int c = NPAR + 1; c < NC; c++)
            if (x[c] > bmv) { bmv = x[c]; am = c; }
        *pptr = (float)am;

        // exp (no max subtraction: logits are O(1)) + Z
        float Z = 0.f;
#pragma unroll
        for (int c = 0; c < NC; c++) {
            float e = __expf(x[c]);
            x[c] = e; Z += e;
        }
        const float invZ = __fdividef(1.f, Z);
        const float lnZ  = __logf(Z);
        const float sc   = valid ? invZ : 0.f;

        // per-class denominator accumulation (registers)
#pragma unroll
        for (int c = 0; c < NC; c++) accA[c] += x[c] * sc;

        // CE + tree-dice intersection via L1-hit reloads
        {
            float xy  = __ldg(pbase + (size_t)ys * NVOX);
            float lpy = xy - lnZ;
            float ce  = sh_mf[ys] * fminf(fmaxf(lpy, L10_LO), L10_HI);
            if (valid) atomicAdd(&sh_in[ys], __expf(lpy));
            if (ypar >= 0) {
                float xp  = __ldg(pbase + (size_t)ypar * NVOX);
                float lpp = xp - lnZ;
                ce += sh_mf[ypar] * fminf(fmaxf(lpp, L10_LO), L10_HI);
                if (valid) atomicAdd(&sh_in[ypar], __expf(lpp));
            }
            if (valid) {
                a_ce -= ce;
                a_vw += 1.f;
                atomicAdd(&sh_hist[am * NC + ys], 1u);
            }
        }

        // sink dice terms
        {
            const int  ppar = (am - NPAR) / NCH;        // am in [4,31]
            const bool mp   = (sh_mf[am] != 0.f);
            const int  s_p  = NPAR + ppar * NCH;
            const bool sib_t    = (ypar >= 0) && (ys != NPAR + ypar * NCH);
            const bool sib_pred = (!mp) && (am != s_p);
            if (valid) {
                if (sib_t)    a_sib |= (1 << ypar);
                if (sib_pred) a_sib |= (1 << ppar);
                const bool sib_p = sib_pred || ((ypar == ppar) && sib_t);
                if (!sib_p) {
                    float psink = ((ppar == 0) ? x[4] : (ppar == 1) ? x[11]
                                 : (ppar == 2) ? x[18] : x[25]) * invZ;
#pragma unroll
                    for (int si = 0; si < 4; si++)
                        if (si == ppar) { a_is[si] += psink; a_ts[si] += 1.f; }
                }
            }
        }

        // bump pointers (compile-time strides)
#pragma unroll
        for (int g = 0; g < 7; g++) pg[g] += TPB;
        pbase += TPB; tptr += TPB; pptr += TPB;
    }

    // ---- block reduction ----
    // warp transpose-reduce of accA: lane l ends with the class-l warp sum
#pragma unroll
    for (int w = 16; w >= 1; w >>= 1) {
#pragma unroll
        for (int i = 0; i < w; i++) {
            float sA = (lane & w) ? accA[i] : accA[i + w];
            float rA = __shfl_xor_sync(0xffffffffu, sA, w);
            accA[i] = ((lane & w) ? accA[i + w] : accA[i]) + rA;
        }
    }
    atomicAdd(&sh_dA[lane], accA[0]);

    float r0 = wred(a_ce), r1 = wred(a_vw);
    float ri0 = wred(a_is[0]), ri1 = wred(a_is[1]), ri2 = wred(a_is[2]), ri3 = wred(a_is[3]);
    float rt0 = wred(a_ts[0]), rt1 = wred(a_ts[1]), rt2 = wred(a_ts[2]), rt3 = wred(a_ts[3]);
    int rs = a_sib;
#pragma unroll
    for (int o = 16; o > 0; o >>= 1) rs |= __shfl_xor_sync(0xffffffffu, rs, o);
    if (lane == 0) {
        atomicAdd(&sh_misc[0], r0);  atomicAdd(&sh_misc[1], r1);
        atomicAdd(&sh_misc[2], ri0); atomicAdd(&sh_misc[3], ri1);
        atomicAdd(&sh_misc[4], ri2); atomicAdd(&sh_misc[5], ri3);
        atomicAdd(&sh_misc[6], rt0); atomicAdd(&sh_misc[7], rt1);
        atomicAdd(&sh_misc[8], rt2); atomicAdd(&sh_misc[9], rt3);
        if (rs) atomicOr(&sh_sib, rs);
    }
    __syncthreads();

    // ---- global accumulation ----
    if (tid < NC) {
        atomicAdd(&g_f[b][tid],      sh_dA[tid]);
        atomicAdd(&g_f[b][NC + tid], sh_in[tid]);
    }
    if (tid >= 64 && tid < 74) atomicAdd(&g_f[b][tid], sh_misc[tid - 64]);
    if (tid == 74 && sh_sib)   atomicOr(&g_sib[b], sh_sib);
    for (int i = tid; i < NC*NC; i += TPB) {
        unsigned h = sh_hist[i];
        if (h) atomicAdd(&g_hist[b][i], h);
    }

    // ---- last-block finalization ----
    __threadfence();
    if (tid == 0) {
        unsigned prev = atomicAdd(&g_count, 1u);
        sh_last = (prev == (unsigned)(NBLK - 1)) ? 1 : 0;
    }
    __syncthreads();
    if (!sh_last) return;

    if (tid < NB * NC) {
        int bb = tid / NC, c = tid % NC;

        float mf = (msk[bb*NC + c] != 0) ? 1.f : 0.f;
        int mem[8]; int nm;
        if (c < NPAR) { nm = 1 + NCH; mem[0] = c; for (int i = 0; i < NCH; i++) mem[1+i] = NPAR + c*NCH + i; }
        else          { nm = 1; mem[0] = c; }
        float tp = 0.f, rsum = 0.f, csum = 0.f;
        for (int i = 0; i < nm; i++) {
            int l = mem[i];
            for (int j = 0; j < nm; j++) tp += (float)g_hist[bb][l*NC + mem[j]];
            for (int t = 0; t < NC; t++) { rsum += (float)g_hist[bb][l*NC + t]; csum += (float)g_hist[bb][t*NC + l]; }
        }
        float* cm = out + 6 + (size_t)(bb*NC + c) * 3;
        cm[0] = tp * mf;
        cm[1] = (rsum - tp) * mf;
        cm[2] = (csum - tp) * mf;

        if (c == 0) {
            float vw = g_f[bb][65];
            float ce = g_f[bb][64] / fmaxf(vw, 1.f);

            float dsum = 0.f, msum = 0.f;
            for (int cc = 0; cc < NC; cc++) {
                float mfc = (msk[bb*NC + cc] != 0) ? 1.f : 0.f;
                float dB = 0.f;
                for (int l = 0; l < NC; l++) dB += (float)g_hist[bb][l*NC + cc];
                if (cc < NPAR)
                    for (int i = 0; i < NCH; i++) {
                        int ch = NPAR + cc*NCH + i;
                        for (int l = 0; l < NC; l++) dB += (float)g_hist[bb][l*NC + ch];
                    }
                float dc = 1.f - 2.f * g_f[bb][NC + cc] / (g_f[bb][cc] + dB + 1e-5f);
                dsum += dc * mfc; msum += mfc;
            }
            float dice = dsum / fmaxf(msum, 1.f);

            float sdsum = 0.f, cnt = 0.f;
            int sib = g_sib[bb];
            for (int si = 0; si < 4; si++) {
                int s = NPAR + si * NCH;
                float d = 1.f - (2.f * g_f[bb][66 + si] + 1e-5f) /
                                (g_f[bb][s] + g_f[bb][70 + si] + 1e-5f);
                float fl = ((sib >> si) & 1) ? 1.f : 0.f;
                sdsum += d * fl; cnt += fl;
            }
            float sink = (cnt > 0.f) ? 0.1f * (sdsum / fmaxf(cnt, 1.f)) : 0.f;
            out[bb*3 + 0] = ce;
            out[bb*3 + 1] = dice;
            out[bb*3 + 2] = sink;
        }
    }

    // reset accumulators for next graph replay
    __syncthreads();
    if (tid < NB*74) ((float*)g_f)[tid] = 0.f;
    if (tid < NB)    g_sib[tid] = 0;
    for (int i = tid; i < NB*NC*NC; i += TPB) ((unsigned*)g_hist)[i] = 0u;
    __threadfence();
    if (tid == 0) g_count = 0u;
}

extern "C" void kernel_launch(void* const* d_in, const int* in_sizes, int n_in,
                              void* d_out, int out_size)
{
    const float* img = (const float*)d_in[0];
    const int*   tgt = (const int*)d_in[1];
    const int*   msk = (const int*)d_in[2];
    float* out = (float*)d_out;

    k_all<<<dim3(NBLKX, NB), TPB>>>(img, tgt, msk, out);
}

// round 6
// speedup vs baseline: 1.1085x; 1.1085x over previous
#include <cuda_runtime.h>

#define NC    32
#define NPAR  4
#define NCH   7
#define NVOX  884736        // 96*96*96
#define NB    2
#define TPB   128
#define PAIRS (TPB/2)       // 64 voxels per iteration per block
#define VPT   16
#define TILE  (PAIRS*VPT)   // 1024
#define NBLKX (NVOX/TILE)   // 864 exact
#define NBLK  (NBLKX*NB)    // 1728

// global accumulators (zero-init at load; last block resets after use)
// g_f layout: [0..31] denomA, [32..63] inter, [64] ce, [65] vw, [66..69] inter_s, [70..73] tgt_s
__device__ float        g_f[NB][74];
__device__ int          g_sib[NB];
__device__ unsigned     g_hist[NB][NC*NC];
__device__ unsigned int g_count;

__device__ __forceinline__ float wred(float v) {
#pragma unroll
    for (int o = 16; o > 0; o >>= 1) v += __shfl_xor_sync(0xffffffffu, v, o);
    return v;
}
// parity-preserving reduce: sums over the 16 same-parity lanes
__device__ __forceinline__ float pwred(float v) {
#pragma unroll
    for (int o = 2; o <= 16; o <<= 1) v += __shfl_xor_sync(0xffffffffu, v, o);
    return v;
}

__global__ __launch_bounds__(TPB, 6)
void k_all(const float* __restrict__ img, const int* __restrict__ tgt,
           const int* __restrict__ msk, float* __restrict__ out)
{
    const int b    = blockIdx.y;
    const int tid  = threadIdx.x;
    const int lane = tid & 31;
    const int q    = tid & 1;          // channel half: 0 -> 0..15, 1 -> 16..31
    const int p    = tid >> 1;         // voxel-pair index within block

    __shared__ float sh_dA[NC], sh_in[NC];
    __shared__ float sh_misc[10];      // ce, vw, is[4], ts[4]
    __shared__ int   sh_sib;
    __shared__ unsigned sh_hist[NC*NC];
    __shared__ float sh_mf[NC];
    __shared__ int   sh_last;

    for (int i = tid; i < NC*NC; i += TPB) sh_hist[i] = 0u;
    if (tid < NC) {
        sh_dA[tid] = 0.f; sh_in[tid] = 0.f;
        sh_mf[tid] = (msk[b*NC + tid] != 0) ? 1.f : 0.f;
    }
    if (tid < 10) sh_misc[tid] = 0.f;
    if (tid == 0) { sh_sib = 0; sh_last = 0; }
    __syncthreads();

    const int v0 = blockIdx.x * TILE + p;
    const float* cb = img + (size_t)b * NC * NVOX + (size_t)(q * 16) * NVOX + v0;
    // anchor pointers for channels lo+{0..15}: anchors 2,7,12,13 -> |imm| <= 2*NVOX*4 bytes
    const float* pA0 = cb + (size_t)2  * NVOX;
    const float* pA1 = cb + (size_t)7  * NVOX;
    const float* pA2 = cb + (size_t)12 * NVOX;
    const float* pA3 = cb + (size_t)13 * NVOX;
    const float* pbase = img + (size_t)b * NC * NVOX + v0;   // CE reloads (even lane)
    const int*   tptr  = tgt + (size_t)b * NVOX + v0;
    float*       pptr  = out + 6 + NB*NC*3 + (size_t)b * NVOX + v0;

    float e[16], accA[16], accI[16];
#pragma unroll
    for (int k = 0; k < 16; k++) { accA[k] = 0.f; accI[k] = 0.f; }
    float a_ce = 0.f, a_vw = 0.f;
    float a_is[2] = {0.f, 0.f};
    float a_ts[2] = {0.f, 0.f};
    int   a_sib = 0;

    const float L10_LO = -16.11809565f;   // log(1e-7)
    const float L10_HI = -1.0000001e-7f;  // log(1 - 1e-7)

#pragma unroll 1
    for (int it = 0; it < VPT; it++) {
        const int y = *tptr;
        const bool valid = (y != 255);
        const int ys = valid ? y : 0;
        const int ypar = (ys >= NPAR) ? (ys - NPAR) / NCH : -1;
        const int tmask = valid ? ((1 << ys) | ((ypar >= 0) ? (1 << ypar) : 0)) : 0;
        const int tl = (tmask >> (q << 4)) & 0xffff;

        // load 16 raw logits via anchored immediates
#pragma unroll
        for (int k = 0; k < 16; k++) {
            const float* pp = (k < 5) ? pA0 : (k < 10) ? pA1 : (k < 14) ? pA2 : pA3;
            const int    A  = (k < 5) ? 2   : (k < 10) ? 7   : (k < 14) ? 12  : 13;
            e[k] = pp[(ptrdiff_t)(k - A) * NVOX];
        }

        // local argmax over leaf channels (global leaves are 4..31)
        float bmv = -1e30f; int aml = 0;
#pragma unroll
        for (int k = 0; k < 16; k++) {
            bool ok = q || (k >= NPAR);
            if (ok && e[k] > bmv) { bmv = e[k]; aml = k; }
        }
        int amg = (q << 4) + aml;
        float ob  = __shfl_xor_sync(0xffffffffu, bmv, 1);
        int   oam = __shfl_xor_sync(0xffffffffu, amg, 1);
        float lob = q ? ob : bmv, hib = q ? bmv : ob;
        int   loa = q ? oam : amg, hia = q ? amg : oam;
        const int am = (lob >= hib) ? loa : hia;   // lowest class wins ties
        if (!q) *pptr = (float)am;

        // exp + pairwise-tree local Z, stitch across the pair
#pragma unroll
        for (int k = 0; k < 16; k++) e[k] = __expf(e[k]);
        float s0 = (e[0]+e[1]) + (e[2]+e[3]);
        float s1 = (e[4]+e[5]) + (e[6]+e[7]);
        float s2 = (e[8]+e[9]) + (e[10]+e[11]);
        float s3 = (e[12]+e[13]) + (e[14]+e[15]);
        float Zl = (s0 + s1) + (s2 + s3);
        float Z  = Zl + __shfl_xor_sync(0xffffffffu, Zl, 1);
        const float invZ = __fdividef(1.f, Z);
        const float lnZ  = __logf(Z);
        const float sc   = valid ? invZ : 0.f;

        // per-class accumulation (registers only)
#pragma unroll
        for (int k = 0; k < 16; k++) {
            float t = e[k] * sc;
            accA[k] += t;
            if ((tl >> k) & 1) accI[k] += t;
        }

        // CE + vw + histogram: even lane only (L1-hit reloads of raw logits)
        if (!q && valid) {
            float xy  = __ldg(pbase + (size_t)ys * NVOX);
            float ce  = sh_mf[ys] * fminf(fmaxf(xy - lnZ, L10_LO), L10_HI);
            if (ypar >= 0) {
                float xp = __ldg(pbase + (size_t)ypar * NVOX);
                ce += sh_mf[ypar] * fminf(fmaxf(xp - lnZ, L10_LO), L10_HI);
            }
            a_ce -= ce;
            a_vw += 1.f;
            atomicAdd(&sh_hist[am * NC + ys], 1u);
        }

        // sink dice: this lane owns groups g = 2q, 2q+1
        {
            const int  ppar = (am - NPAR) / NCH;
            const bool mp   = (sh_mf[am] != 0.f);
            const float sv0 = q ? e[2] : e[4];    // sink channel of group 2q
            const float sv1 = q ? e[9] : e[11];   // sink channel of group 2q+1
#pragma unroll
            for (int l = 0; l < 2; l++) {
                const int g   = (q << 1) + l;
                const int sch = NPAR + NCH * g;
                bool sib = ((ypar == g) && (ys != sch)) ||
                           ((!mp) && (ppar == g) && (am != sch));
                if (valid) {
                    if (sib) a_sib |= (1 << g);
                    if ((ppar == g) && !sib) {
                        a_is[l] += (l ? sv1 : sv0) * invZ;
                        a_ts[l] += 1.f;
                    }
                }
            }
        }

        pA0 += PAIRS; pA1 += PAIRS; pA2 += PAIRS; pA3 += PAIRS;
        pbase += PAIRS; tptr += PAIRS; pptr += PAIRS;
    }

    // ---- block reduction ----
    // parity butterfly: same-parity lanes sum; lane 0 = classes 0..15, lane 1 = 16..31
#pragma unroll
    for (int k = 0; k < 16; k++) { accA[k] = pwred(accA[k]); accI[k] = pwred(accI[k]); }
    a_is[0] = pwred(a_is[0]); a_is[1] = pwred(a_is[1]);
    a_ts[0] = pwred(a_ts[0]); a_ts[1] = pwred(a_ts[1]);
    float r_ce = wred(a_ce), r_vw = wred(a_vw);
    int rs = a_sib;
#pragma unroll
    for (int o = 16; o > 0; o >>= 1) rs |= __shfl_xor_sync(0xffffffffu, rs, o);

    if (lane < 2) {
#pragma unroll
        for (int k = 0; k < 16; k++) {
            atomicAdd(&sh_dA[(lane << 4) + k], accA[k]);
            atomicAdd(&sh_in[(lane << 4) + k], accI[k]);
        }
        atomicAdd(&sh_misc[2 + (lane << 1) + 0], a_is[0]);
        atomicAdd(&sh_misc[2 + (lane << 1) + 1], a_is[1]);
        atomicAdd(&sh_misc[6 + (lane << 1) + 0], a_ts[0]);
        atomicAdd(&sh_misc[6 + (lane << 1) + 1], a_ts[1]);
    }
    if (lane == 0) {
        atomicAdd(&sh_misc[0], r_ce);
        atomicAdd(&sh_misc[1], r_vw);
        if (rs) atomicOr(&sh_sib, rs);
    }
    __syncthreads();

    // ---- global accumulation ----
    if (tid < NC) {
        atomicAdd(&g_f[b][tid],      sh_dA[tid]);
        atomicAdd(&g_f[b][NC + tid], sh_in[tid]);
    }
    if (tid >= 64 && tid < 74) atomicAdd(&g_f[b][tid], sh_misc[tid - 64]);
    if (tid == 74 && sh_sib)   atomicOr(&g_sib[b], sh_sib);
    for (int i = tid; i < NC*NC; i += TPB) {
        unsigned h = sh_hist[i];
        if (h) atomicAdd(&g_hist[b][i], h);
    }

    // ---- last-block finalization ----
    __threadfence();
    if (tid == 0) {
        unsigned prev = atomicAdd(&g_count, 1u);
        sh_last = (prev == (unsigned)(NBLK - 1)) ? 1 : 0;
    }
    __syncthreads();
    if (!sh_last) return;

    if (tid < NB * NC) {
        int bb = tid / NC, c = tid % NC;

        float mf = (msk[bb*NC + c] != 0) ? 1.f : 0.f;
        int mem[8]; int nm;
        if (c < NPAR) { nm = 1 + NCH; mem[0] = c; for (int i = 0; i < NCH; i++) mem[1+i] = NPAR + c*NCH + i; }
        else          { nm = 1; mem[0] = c; }
        float tp = 0.f, rsum = 0.f, csum = 0.f;
        for (int i = 0; i < nm; i++) {
            int l = mem[i];
            for (int j = 0; j < nm; j++) tp += (float)g_hist[bb][l*NC + mem[j]];
            for (int t = 0; t < NC; t++) { rsum += (float)g_hist[bb][l*NC + t]; csum += (float)g_hist[bb][t*NC + l]; }
        }
        float* cm = out + 6 + (size_t)(bb*NC + c) * 3;
        cm[0] = tp * mf;
        cm[1] = (rsum - tp) * mf;
        cm[2] = (csum - tp) * mf;

        if (c == 0) {
            float vw = g_f[bb][65];
            float ce = g_f[bb][64] / fmaxf(vw, 1.f);

            float dsum = 0.f, msum = 0.f;
            for (int cc = 0; cc < NC; cc++) {
                float mfc = (msk[bb*NC + cc] != 0) ? 1.f : 0.f;
                float dB = 0.f;
                for (int l = 0; l < NC; l++) dB += (float)g_hist[bb][l*NC + cc];
                if (cc < NPAR)
                    for (int i = 0; i < NCH; i++) {
                        int ch = NPAR + cc*NCH + i;
                        for (int l = 0; l < NC; l++) dB += (float)g_hist[bb][l*NC + ch];
                    }
                float dc = 1.f - 2.f * g_f[bb][NC + cc] / (g_f[bb][cc] + dB + 1e-5f);
                dsum += dc * mfc; msum += mfc;
            }
            float dice = dsum / fmaxf(msum, 1.f);

            float sdsum = 0.f, cnt = 0.f;
            int sib = g_sib[bb];
            for (int si = 0; si < 4; si++) {
                int s = NPAR + si * NCH;
                float d = 1.f - (2.f * g_f[bb][66 + si] + 1e-5f) /
                                (g_f[bb][s] + g_f[bb][70 + si] + 1e-5f);
                float fl = ((sib >> si) & 1) ? 1.f : 0.f;
                sdsum += d * fl; cnt += fl;
            }
            float sink = (cnt > 0.f) ? 0.1f * (sdsum / fmaxf(cnt, 1.f)) : 0.f;
            out[bb*3 + 0] = ce;
            out[bb*3 + 1] = dice;
            out[bb*3 + 2] = sink;
        }
    }

    // reset accumulators for next graph replay (STRIDED: TPB-independent coverage)
    __syncthreads();
    for (int i = tid; i < NB*74; i += TPB)    ((float*)g_f)[i] = 0.f;
    for (int i = tid; i < NB; i += TPB)       g_sib[i] = 0;
    for (int i = tid; i < NB*NC*NC; i += TPB) ((unsigned*)g_hist)[i] = 0u;
    __threadfence();
    if (tid == 0) g_count = 0u;
}

extern "C" void kernel_launch(void* const* d_in, const int* in_sizes, int n_in,
                              void* d_out, int out_size)
{
    const float* img = (const float*)d_in[0];
    const int*   tgt = (const int*)d_in[1];
    const int*   msk = (const int*)d_in[2];
    float* out = (float*)d_out;

    k_all<<<dim3(NBLKX, NB), TPB>>>(img, tgt, msk, out);
}